// round 12
// baseline (speedup 1.0000x reference)
#include <cuda_runtime.h>
#include <math_constants.h>

// LLaDA2 group-limited router, GB300 sm_103a — round 12.
// Base = R7 (best-profiled variant) + R8's exact 3-FMNMX butterfly.
// New: pass-A sigmoid elementwise chain uses packed mul.rn.f32x2 /
// add.rn.f32x2 (bit-identical rounding to scalar FMUL/FADD), cutting
// 12 float instrs per lane-token. Bias pairs pre-packed per thread.

#define NUM_EXPERTS 256
#define TOPK 8
#define TOPKG 4
#define ROUTER_SCALE 2.5f
#define NEG_INF (-CUDART_INF_F)

#define GROW 36                 // floats per padded 32-expert group row (144B)
#define TROW (8 * GROW)
#define WROWS (4 * TROW)
#define NWARPS 4                // 128 threads per block

// ---- packed f32x2 helpers (sm_100+; same RN rounding as scalar) ----
static __device__ __forceinline__ unsigned long long pk2(float lo, float hi) {
    unsigned long long r;
    asm("mov.b64 %0, {%1, %2};" : "=l"(r) : "f"(lo), "f"(hi));
    return r;
}
static __device__ __forceinline__ void upk2(float& lo, float& hi, unsigned long long p) {
    asm("mov.b64 {%0, %1}, %2;" : "=f"(lo), "=f"(hi) : "l"(p));
}
static __device__ __forceinline__ unsigned long long mul2(unsigned long long a,
                                                          unsigned long long b) {
    unsigned long long r;
    asm("mul.rn.f32x2 %0, %1, %2;" : "=l"(r) : "l"(a), "l"(b));
    return r;
}
static __device__ __forceinline__ unsigned long long add2(unsigned long long a,
                                                          unsigned long long b) {
    unsigned long long r;
    asm("add.rn.f32x2 %0, %1, %2;" : "=l"(r) : "l"(a), "l"(b));
    return r;
}

// ---- scalar keyed CE (descending); ties keep first arg ----
static __device__ __forceinline__ void cef(float& ka, unsigned& xa,
                                           float& kb, unsigned& xb) {
    float kx = fmaxf(ka, kb);
    float kn = fminf(ka, kb);
    bool t = (kb > ka);
    unsigned ix = t ? xb : xa;
    unsigned in_ = t ? xa : xb;
    ka = kx; kb = kn; xa = ix; xb = in_;
}
static __device__ __forceinline__ void maxsel(float& lk, unsigned& li,
                                              float ck, unsigned ci) {
    bool t = (ck > lk);
    lk = fmaxf(lk, ck);
    li = t ? ci : li;
}

// Batcher 8-input sorting network (19 CE), descending.
static __device__ __forceinline__ void sort8(float k[8], unsigned x[8]) {
    cef(k[0],x[0],k[1],x[1]); cef(k[2],x[2],k[3],x[3]);
    cef(k[4],x[4],k[5],x[5]); cef(k[6],x[6],k[7],x[7]);
    cef(k[0],x[0],k[2],x[2]); cef(k[1],x[1],k[3],x[3]);
    cef(k[4],x[4],k[6],x[6]); cef(k[5],x[5],k[7],x[7]);
    cef(k[1],x[1],k[2],x[2]); cef(k[5],x[5],k[6],x[6]);
    cef(k[0],x[0],k[4],x[4]); cef(k[1],x[1],k[5],x[5]);
    cef(k[2],x[2],k[6],x[6]); cef(k[3],x[3],k[7],x[7]);
    cef(k[2],x[2],k[4],x[4]); cef(k[3],x[3],k[5],x[5]);
    cef(k[1],x[1],k[2],x[2]); cef(k[3],x[3],k[4],x[4]); cef(k[5],x[5],k[6],x[6]);
}

// L := top-8 of L ∪ C (both sorted desc): 8 max-selects + 12-CE bitonic clean.
static __device__ __forceinline__ void merge8(float Lk[8], unsigned Li[8],
                                              const float Ck[8], const unsigned Ci[8]) {
#pragma unroll
    for (int i = 0; i < 8; ++i) maxsel(Lk[i], Li[i], Ck[7 - i], Ci[7 - i]);
    cef(Lk[0],Li[0],Lk[4],Li[4]); cef(Lk[1],Li[1],Lk[5],Li[5]);
    cef(Lk[2],Li[2],Lk[6],Li[6]); cef(Lk[3],Li[3],Lk[7],Li[7]);
    cef(Lk[0],Li[0],Lk[2],Li[2]); cef(Lk[1],Li[1],Lk[3],Li[3]);
    cef(Lk[4],Li[4],Lk[6],Li[6]); cef(Lk[5],Li[5],Lk[7],Li[7]);
    cef(Lk[0],Li[0],Lk[1],Li[1]); cef(Lk[2],Li[2],Lk[3],Li[3]);
    cef(Lk[4],Li[4],Lk[5],Li[5]); cef(Lk[6],Li[6],Lk[7],Li[7]);
}

__global__ void __launch_bounds__(128)
router_kernel(const float* __restrict__ logits,
              const float* __restrict__ bias,
              float* __restrict__ out_w,
              float* __restrict__ out_i,
              int T) {
    __shared__ float skey[NWARPS * WROWS];   // 18432 B

    const int warp = threadIdx.x >> 5;
    const int lane = threadIdx.x & 31;
    float* wk = skey + warp * WROWS;

    const int tok0 = blockIdx.x * (NWARPS * 4) + warp * 4;

    float4 bv0 = __ldg((const float4*)(bias + lane * 8));
    float4 bv1 = __ldg((const float4*)(bias + lane * 8 + 4));

    // pre-packed constants and bias pairs (once per thread)
    const float nl2e = __uint_as_float(0xBFB8AA3Bu);   // -(float)log2(e), __expf's constant
    const unsigned long long cL  = pk2(nl2e, nl2e);
    const unsigned long long oneP = pk2(1.0f, 1.0f);
    unsigned long long bbp[4] = { pk2(bv0.x, bv0.y), pk2(bv0.z, bv0.w),
                                  pk2(bv1.x, bv1.y), pk2(bv1.z, bv1.w) };

    const int g_mine = lane >> 2;
    const int q = lane & 3;

    // ---- Pass A (coalesced): keys -> smem; exact group top-2 scores ----
    float gs_t[4];
#pragma unroll
    for (int t = 0; t < 4; ++t) {
        int tk = min(tok0 + t, T - 1);
        const float* lp = logits + (size_t)tk * NUM_EXPERTS + lane * 8;
        float4 x0 = __ldg((const float4*)lp);
        float4 x1 = __ldg((const float4*)(lp + 4));
        float v[8] = {x0.x, x0.y, x0.z, x0.w, x1.x, x1.y, x1.z, x1.w};
        float k[8];
#pragma unroll
        for (int j = 0; j < 8; j += 2) {
            // sigmoid(x) = rcp(1 + exp2(x * -log2e)), then + bias.
            // Packed mul/add round identically to scalar FMUL/FADD ->
            // keys bit-identical to the scalar __expf path.
            unsigned long long pp = mul2(pk2(v[j], v[j + 1]), cL);
            float p0, p1; upk2(p0, p1, pp);
            float e0, e1;
            asm("ex2.approx.f32 %0, %1;" : "=f"(e0) : "f"(p0));
            asm("ex2.approx.f32 %0, %1;" : "=f"(e1) : "f"(p1));
            unsigned long long dp = add2(pk2(e0, e1), oneP);
            float d0, d1; upk2(d0, d1, dp);
            float s0, s1;
            asm("rcp.approx.f32 %0, %1;" : "=f"(s0) : "f"(d0));
            asm("rcp.approx.f32 %0, %1;" : "=f"(s1) : "f"(d1));
            unsigned long long kp = add2(pk2(s0, s1), bbp[j >> 1]);
            upk2(k[j], k[j + 1], kp);
        }

        float* dst = wk + t * TROW + g_mine * GROW + q * 8;
        *(float4*)dst       = make_float4(k[0], k[1], k[2], k[3]);
        *(float4*)(dst + 4) = make_float4(k[4], k[5], k[6], k[7]);

        float m1 = fmaxf(k[0], k[1]);
        float m2 = fminf(k[0], k[1]);
#pragma unroll
        for (int j = 2; j < 8; ++j) {
            m2 = fmaxf(m2, fminf(m1, k[j]));
            m1 = fmaxf(m1, k[j]);
        }
        // quad butterfly: exact top-2 of the group's 32 (3 FMNMX per step)
#pragma unroll
        for (int m = 1; m < 4; m <<= 1) {
            float o1 = __shfl_xor_sync(0xffffffffu, m1, m);
            float o2 = __shfl_xor_sync(0xffffffffu, m2, m);
            m2 = fmaxf(fminf(m1, o1), fmaxf(m2, o2));
            m1 = fmaxf(m1, o1);
        }
        gs_t[t] = m1 + m2;
    }
    __syncwarp();

    // ---- Octet phase ----
    const int sub = lane & 7;
    const int oct = lane >> 3;

    float g0 = __shfl_sync(0xffffffffu, gs_t[0], sub * 4);
    float g1 = __shfl_sync(0xffffffffu, gs_t[1], sub * 4);
    float g2 = __shfl_sync(0xffffffffu, gs_t[2], sub * 4);
    float g3 = __shfl_sync(0xffffffffu, gs_t[3], sub * 4);
    float gs = (oct == 0) ? g0 : (oct == 1) ? g1 : (oct == 2) ? g2 : g3;

    int rank = 0;
#pragma unroll
    for (int g = 1; g < 8; ++g) {
        float og = __shfl_xor_sync(0xffffffffu, gs, g, 8);
        int osub = sub ^ g;
        rank += (og > gs || (og == gs && osub < sub)) ? 1 : 0;
    }

    unsigned nm = (rank < TOPKG) ? ((unsigned)sub << (rank * 4)) : 0u;
    nm |= __shfl_xor_sync(0xffffffffu, nm, 1, 8);
    nm |= __shfl_xor_sync(0xffffffffu, nm, 2, 8);
    nm |= __shfl_xor_sync(0xffffffffu, nm, 4, 8);
    const int gsel = (nm >> ((sub >> 1) * 4)) & 7;
    const int half = sub & 1;

    // ---- Pass B: keyed top-8 of my 16 keys (distinct per lane) ----
    const float* src = wk + oct * TROW + gsel * GROW + half * 16;
    float4 a0 = *(const float4*)(src);
    float4 a1 = *(const float4*)(src + 4);
    float4 a2 = *(const float4*)(src + 8);
    float4 a3 = *(const float4*)(src + 12);
    const unsigned ibase = (unsigned)(gsel * 32 + half * 16);

    float Ak[8] = {a0.x, a0.y, a0.z, a0.w, a1.x, a1.y, a1.z, a1.w};
    float Bk[8] = {a2.x, a2.y, a2.z, a2.w, a3.x, a3.y, a3.z, a3.w};
    unsigned Ai[8], Bi[8];
#pragma unroll
    for (int j = 0; j < 8; ++j) { Ai[j] = ibase + j; Bi[j] = ibase + 8 + j; }
    sort8(Ak, Ai);
    sort8(Bk, Bi);
    merge8(Ak, Ai, Bk, Bi);                 // sorted top-8 of my 16

    // ---- Extraction: global top-8 across 8 distinct lists (masks 1,2,4) ----
    float mykey = 0.0f; unsigned myidx = 0u;
#pragma unroll
    for (int r = 0; r < TOPK; ++r) {
        float hk = Ak[0]; unsigned hi = Ai[0];
#pragma unroll
        for (int m = 1; m < 8; m <<= 1) {
            float ok    = __shfl_xor_sync(0xffffffffu, hk, m, 8);
            unsigned oi = __shfl_xor_sync(0xffffffffu, hi, m, 8);
            bool take = (ok > hk) || (ok == hk && oi < hi);
            hk = take ? ok : hk;
            hi = take ? oi : hi;
        }
        if (sub == r) { mykey = hk; myidx = hi; }
        bool win = (hi == Ai[0]);           // ids unique -> exactly one lane
#pragma unroll
        for (int j = 0; j < 7 - r; ++j) {
            Ak[j] = win ? Ak[j + 1] : Ak[j];
            Ai[j] = win ? Ai[j + 1] : Ai[j];
        }
        if (r == 0) Ak[7] = win ? NEG_INF : Ak[7];
    }

    // ---- Phase 4: weight = sigmoid score, renormalize, scale ----
    float bvw = __ldg(bias + myidx);
    float score = mykey - bvw;

    float wsum = score;
#pragma unroll
    for (int m = 1; m < 8; m <<= 1)
        wsum += __shfl_xor_sync(0xffffffffu, wsum, m, 8);

    float w = score * __fdividef(ROUTER_SCALE, wsum + 1e-20f);

    if (tok0 + oct < T) {
        size_t o = (size_t)tok0 * TOPK + lane;
        out_w[o] = w;
        if (out_i) out_i[o] = (float)myidx;
    }
}

extern "C" void kernel_launch(void* const* d_in, const int* in_sizes, int n_in,
                              void* d_out, int out_size) {
    const float* logits = (const float*)d_in[0];
    const float* bias   = (n_in > 1) ? (const float*)d_in[1] : nullptr;
    int s0 = in_sizes[0];
    int s1 = (n_in > 1) ? in_sizes[1] : 0;
    if (s0 == NUM_EXPERTS && s1 > NUM_EXPERTS) {
        const float* tp = logits; logits = bias; bias = tp;
        int ts = s0; s0 = s1; s1 = ts;
    }
    int T = s0 / NUM_EXPERTS;

    float* out_w = (float*)d_out;
    float* out_i = (out_size >= T * 2 * TOPK) ? (out_w + (size_t)T * TOPK) : nullptr;

    int tokens_per_block = NWARPS * 4;
    dim3 grid((T + tokens_per_block - 1) / tokens_per_block);
    router_kernel<<<grid, NWARPS * 32>>>(logits, bias, out_w, out_i, T);
}